// round 14
// baseline (speedup 1.0000x reference)
#include <cuda_runtime.h>
#include <cuda_fp16.h>
#include <math.h>
#include <stdint.h>

#define NN 10000
#define NE 160000
#define NB 10
#define RN 100
#define WN 704
#define NCH 11
#define EB 128
#define HS 130        /* hh row stride in halves (conflict-free) */

#define SQ3    1.7320508075688772f
#define ISQ3   0.5773502691896258f
#define SQ75   2.7386127875258306f
#define C_SC   0.25f
#define C_V0   0.35355339059327373f
#define C_CG   0.20412414523193152f
#define I24    0.20412414523193152f
#define I32    0.17677669529663687f
#define I8     0.35355339059327373f
#define I16    0.25f
#define THIRD  0.3333333333333333f

__device__ float g_rbf[NE*NB];
__device__ float g_sh1[NE*3];
__device__ float g_s[NN*16];
__device__ float g_v[NN*24];
__device__ float g_aggs[NN*24];
__device__ float g_aggv[NN*128];       /* [N][32][4] for float4 atomics */
__device__ uint4 g_btf[4*NCH*32*32];   /* pre-baked B fragments: [l][c][fragidx][lane] */
__device__ float g_rwT[4*RN*12];       /* radial w transposed: [l][r][10 w + bias + pad] */

/* ---- msg smem: hh (128*130*2=33280) U feat (128*77*4=39424) ; col @39424 ---- */
#define OFF_U    0
#define OFF_COL  39424
#define SM_TOT   39936
#define FST 77

__device__ __forceinline__ uint32_t smem_u32(const void* p){
    uint32_t a; asm("{ .reg .u64 t; cvta.to.shared.u64 t, %1; cvt.u32.u64 %0, t; }":"=r"(a):"l"(p)); return a;
}
__device__ __forceinline__ void ldsm4(uint32_t* r, uint32_t a){
    asm volatile("ldmatrix.sync.aligned.m8n8.x4.shared.b16 {%0,%1,%2,%3}, [%4];"
        :"=r"(r[0]),"=r"(r[1]),"=r"(r[2]),"=r"(r[3]):"r"(a));
}
__device__ __forceinline__ void mma16816(float* d, const uint32_t* a, uint32_t b0, uint32_t b1){
    asm volatile("mma.sync.aligned.m16n8k16.row.col.f32.f16.f16.f32 "
        "{%0,%1,%2,%3}, {%4,%5,%6,%7}, {%8,%9}, {%0,%1,%2,%3};"
        : "+f"(d[0]),"+f"(d[1]),"+f"(d[2]),"+f"(d[3])
        : "r"(a[0]),"r"(a[1]),"r"(a[2]),"r"(a[3]),"r"(b0),"r"(b1));
}
__device__ __forceinline__ void red2(float* p, float a, float b){
    atomicAdd((float2*)p, make_float2(a,b));
}
__device__ __forceinline__ void red4(float* p, float a, float b, float c){
    atomicAdd((float4*)p, make_float4(a,b,c,0.f));
}

/* ---------------- geometry ---------------- */
__global__ void geom_kernel(const float* __restrict__ pos, const int* __restrict__ row, const int* __restrict__ col){
    int e = blockIdx.x*256 + threadIdx.x;
    if (e >= NE) return;
    int r = row[e], c = col[e];
    float vx = pos[3*r]-pos[3*c], vy = pos[3*r+1]-pos[3*c+1], vz = pos[3*r+2]-pos[3*c+2];
    float len = sqrtf(vx*vx+vy*vy+vz*vz+1e-12f);
    float inv = 1.0f/len;
    g_sh1[3*e]=SQ3*vx*inv; g_sh1[3*e+1]=SQ3*vy*inv; g_sh1[3*e+2]=SQ3*vz*inv;
    const float step = 10.0f/9.0f;
#pragma unroll
    for (int k=0;k<NB;k++){ float d = len - (float)k*step; g_rbf[e*NB+k] = expf(-0.405f*d*d); }
}

/* ---------------- init ---------------- */
__global__ void init_kernel(const float* __restrict__ x, const float* __restrict__ ew){
    int idx = blockIdx.x*blockDim.x + threadIdx.x;
    int nt = gridDim.x*blockDim.x;
    if (idx < NN*16){
        int n = idx>>4, t = idx&15;
        float a = 0.f;
#pragma unroll
        for (int k=0;k<8;k++) a += x[n*8+k]*ew[k*16+t];
        g_s[idx] = a*I8;
    }
    for (int i=idx;i<NN*24;i+=nt){ g_v[i]=0.f; g_aggs[i]=0.f; }
    for (int i=idx;i<NN*128;i+=nt) g_aggv[i]=0.f;
}

/* ---------------- one-time: radial transpose ---------------- */
__global__ void conv_rwt(const float* __restrict__ rw, const float* __restrict__ rb){
    int idx = blockIdx.x*256 + threadIdx.x;
    if (idx >= 4*RN*12) return;
    int j = idx % 12;
    int r = (idx/12) % RN;
    int l = idx / (RN*12);
    float v = 0.f;
    if (j < 10)       v = rw[l*1000 + j*100 + r];
    else if (j == 10) v = rb[l*100 + r];
    g_rwT[idx] = v;
}

/* ---------------- one-time: bake B fragments (stage+swizzle+ldsm, dump regs) ----------------
   block = (l, chunk); 128 threads. Replicates msg's staging layout exactly, then
   each warp ldsm4's 8 of the 32 fragidx and stores uint4 -> g_btf.                */
__global__ void conv_frag(const float* __restrict__ fcw, const float* __restrict__ fcb){
    __shared__ uint16_t bs[8192];            /* 64 n x 128 k fp16, swizzled, 16KB */
    int l = blockIdx.x / NCH, c = blockIdx.x % NCH;
    int tid = threadIdx.x;
    int wid = tid>>5, lane = tid&31;
    int rowin = lane&7, mi = lane>>3;

    for (int idx=tid; idx<8192; idx+=128){
        int n = idx>>7, k = idx&127;         /* n = col within chunk, k = K row */
        int cg = c*64 + n;
        float v = 0.f;
        if (k < 100)       v = fcw[(size_t)(l*RN + k)*WN + cg];
        else if (k == 100) v = fcb[l*WN + cg];
        __half h = __float2half_rn(v);
        uint32_t byte = (uint32_t)(n*256 + (((k>>3) ^ (n&7))<<4) + (k&7)*2);
        bs[byte>>1] = *(uint16_t*)&h;
    }
    __syncthreads();

    uint32_t sb = smem_u32(bs);
#pragma unroll
    for (int t=0;t<8;t++){
        int fragidx = wid*8 + t;
        int p = fragidx>>4, q4 = (fragidx>>2)&3, nf = fragidx&3;
        int nfg = p*4 + nf;
        uint32_t bm[4];
        ldsm4(bm, sb + (((nfg*8 + rowin)*16 + ((q4*4+mi) ^ rowin)) << 4));
        g_btf[((size_t)(l*NCH + c)*32 + fragidx)*32 + lane] =
            make_uint4(bm[0], bm[1], bm[2], bm[3]);
    }
}

/* ---------------- fused HMMA message kernel: sync-free, B via global fragments ---------------- */
__global__ void __launch_bounds__(128, 3)
msg_kernel(int l, const int* __restrict__ row, const int* __restrict__ col){
    extern __shared__ char smem[];
    int tid = threadIdx.x;
    int wid = tid>>5, lane = tid&31;
    int g = lane>>2, tig = lane&3;
    int tq = tig*2;
    int e0 = blockIdx.x*EB;

    uint16_t* hh = (uint16_t*)(smem + OFF_U);
    float*    featf = (float*)(smem + OFF_U);
    int*      colsm = (int*)(smem + OFF_COL);

    /* h compute: thread = edge (warp-local rows) */
    {
        int eg = e0 + tid;
        float rbf[NB];
        const float2* rb2 = (const float2*)(g_rbf + (size_t)eg*NB);
#pragma unroll
        for (int i=0;i<5;i++){ float2 v = rb2[i]; rbf[i*2]=v.x; rbf[i*2+1]=v.y; }
        const float4* wt = (const float4*)(g_rwT + l*RN*12);
        uint16_t* hrow = hh + tid*HS;
#pragma unroll 4
        for (int r=0;r<RN;r++){
            float4 c0 = wt[r*3], c1 = wt[r*3+1], c2 = wt[r*3+2];
            float a = c2.z
                + rbf[0]*c0.x + rbf[1]*c0.y + rbf[2]*c0.z + rbf[3]*c0.w
                + rbf[4]*c1.x + rbf[5]*c1.y + rbf[6]*c1.z + rbf[7]*c1.w
                + rbf[8]*c2.x + rbf[9]*c2.y;
            a = fmaxf(a, 0.f);
            __half hv = __float2half_rn(a);
            hrow[r] = *(uint16_t*)&hv;
        }
        hrow[100] = 0x3C00;                 /* bias row: A = 1.0 */
#pragma unroll
        for (int r=101;r<112;r++) hrow[r] = 0;
    }
    __syncwarp();

    /* A fragment preload: warp strip = 32 edges (rows r0,+8,+16,+24) */
    uint32_t A0[28], A1[28];
    int r0 = wid*32 + g;
    {
#pragma unroll
        for (int ks=0;ks<7;ks++){
            int k0 = ks*16 + tq;
            A0[ks*4+0] = *(uint32_t*)&hh[r0*HS + k0];
            A0[ks*4+1] = *(uint32_t*)&hh[(r0+8)*HS + k0];
            A0[ks*4+2] = *(uint32_t*)&hh[r0*HS + k0+8];
            A0[ks*4+3] = *(uint32_t*)&hh[(r0+8)*HS + k0+8];
            A1[ks*4+0] = *(uint32_t*)&hh[(r0+16)*HS + k0];
            A1[ks*4+1] = *(uint32_t*)&hh[(r0+24)*HS + k0];
            A1[ks*4+2] = *(uint32_t*)&hh[(r0+16)*HS + k0+8];
            A1[ks*4+3] = *(uint32_t*)&hh[(r0+24)*HS + k0+8];
        }
    }
    __syncwarp();   /* hh (this warp's rows) dead; feat overlays */

    /* features + col: thread = edge (warp-local rows) */
    {
        int e = tid, eg = e0 + e;
        int rr = row[eg];
        colsm[e] = col[eg];
        float* F = featf + e*FST;
#pragma unroll
        for (int t=0;t<16;t++) F[t] = g_s[rr*16+t];
#pragma unroll
        for (int i=0;i<24;i++) F[16+i] = g_v[rr*24+i];
        float s1x = g_sh1[eg*3], s1y = g_sh1[eg*3+1], s1z = g_sh1[eg*3+2];
        F[72]=s1x; F[73]=s1y; F[74]=s1z;
        float ux=s1x*ISQ3, uy=s1y*ISQ3, uz=s1z*ISQ3;
#pragma unroll
        for (int u=0;u<8;u++){
            float vx=F[16+u*3], vy=F[17+u*3], vz=F[18+u*3];
            float dot = ux*vx+uy*vy+uz*vz;
            F[40+u] = SQ3*dot;
            F[48+u*3] = SQ75*(dot*ux - vx*THIRD);
            F[49+u*3] = SQ75*(dot*uy - vy*THIRD);
            F[50+u*3] = SQ75*(dot*uz - vz*THIRD);
        }
    }
    __syncwarp();

    const float* Fp0 = featf + r0*FST;
    const float* Fp1 = featf + (r0+8)*FST;
    const float* Fp2 = featf + (r0+16)*FST;
    const float* Fp3 = featf + (r0+24)*FST;
    int cn0 = colsm[r0], cn1 = colsm[r0+8], cn2 = colsm[r0+16], cn3 = colsm[r0+24];
    float m0[16], m1[16];
    const uint4* bbase = g_btf + (size_t)l*NCH*1024 + lane;

#pragma unroll
    for (int c=0;c<NCH;c++){
        const uint4* bc = bbase + c*1024;

        float a8[24];
        float a9[8];
        if (c >= 8){
#pragma unroll
            for (int i=0;i<24;i++) a8[i]=0.f;
#pragma unroll
            for (int i=0;i<8;i++)  a9[i]=0.f;
        }
        if (c == 0){
#pragma unroll
            for (int i=0;i<16;i++) m0[i]=0.f;
        }
        if (c == 4){
#pragma unroll
            for (int i=0;i<16;i++) m1[i]=0.f;
        }

#pragma unroll
        for (int p=0;p<2;p++){
            float acc0[16], acc1[16];
#pragma unroll
            for (int i=0;i<16;i++){ acc0[i]=0.f; acc1[i]=0.f; }
            /* B fragments via coalesced global loads, double-buffered across q4 */
            uint4 ba[4], bb2[4];
#pragma unroll
            for (int nf=0;nf<4;nf++) ba[nf] = __ldg(bc + (p*16 + nf)*32);
#pragma unroll
            for (int q4=0;q4<4;q4++){
                if (q4 < 3){
#pragma unroll
                    for (int nf=0;nf<4;nf++){
                        uint4 v = __ldg(bc + (p*16 + (q4+1)*4 + nf)*32);
                        if (q4&1) ba[nf] = v; else bb2[nf] = v;
                    }
                }
#pragma unroll
                for (int nf=0;nf<4;nf++){
                    uint4 bm = (q4&1) ? bb2[nf] : ba[nf];
                    mma16816(acc0 + nf*4, A0 + (2*q4)*4, bm.x, bm.y);
                    mma16816(acc1 + nf*4, A1 + (2*q4)*4, bm.x, bm.y);
                    if (q4 < 3){
                        mma16816(acc0 + nf*4, A0 + (2*q4+1)*4, bm.z, bm.w);
                        mma16816(acc1 + nf*4, A1 + (2*q4+1)*4, bm.z, bm.w);
                    }
                }
            }
            /* consume pass */
            if (c < 4){
#pragma unroll
                for (int nf=0;nf<4;nf++){
                    int u = c*4 + p*2 + (nf>>1);
                    int sl = (nf&1)*2;
                    float s0 = Fp0[u], s1 = Fp1[u], s2 = Fp2[u], s3 = Fp3[u];
                    m0[sl+0]  += acc0[nf*4+0]*s0;  m0[sl+1]  += acc0[nf*4+1]*s0;
                    m0[4+sl]  += acc0[nf*4+2]*s1;  m0[5+sl]  += acc0[nf*4+3]*s1;
                    m0[8+sl]  += acc1[nf*4+0]*s2;  m0[9+sl]  += acc1[nf*4+1]*s2;
                    m0[12+sl] += acc1[nf*4+2]*s3;  m0[13+sl] += acc1[nf*4+3]*s3;
                }
            } else if (c < 8){
#pragma unroll
                for (int nf=0;nf<4;nf++){
                    int u = (c-4)*4 + p*2 + (nf>>1);
                    int sl = (nf&1)*2;
                    float s0 = Fp0[u], s1 = Fp1[u], s2 = Fp2[u], s3 = Fp3[u];
                    m1[sl+0]  += acc0[nf*4+0]*s0;  m1[sl+1]  += acc0[nf*4+1]*s0;
                    m1[4+sl]  += acc0[nf*4+2]*s1;  m1[5+sl]  += acc0[nf*4+3]*s1;
                    m1[8+sl]  += acc1[nf*4+0]*s2;  m1[9+sl]  += acc1[nf*4+1]*s2;
                    m1[12+sl] += acc1[nf*4+2]*s3;  m1[13+sl] += acc1[nf*4+3]*s3;
                }
            } else if (c == 9){
#pragma unroll
                for (int nf=0;nf<4;nf++){
                    int u = p*4 + nf;
                    a9[0] += acc0[nf*4+0]*Fp0[40+u];  a9[1] += acc0[nf*4+1]*Fp0[40+u];
                    a9[2] += acc0[nf*4+2]*Fp1[40+u];  a9[3] += acc0[nf*4+3]*Fp1[40+u];
                    a9[4] += acc1[nf*4+0]*Fp2[40+u];  a9[5] += acc1[nf*4+1]*Fp2[40+u];
                    a9[6] += acc1[nf*4+2]*Fp3[40+u];  a9[7] += acc1[nf*4+3]*Fp3[40+u];
                }
            } else {  /* c==8 or c==10 */
                int fb = (c==8) ? 16 : 48;
#pragma unroll
                for (int nf=0;nf<4;nf++){
                    int u = p*4 + nf;
#pragma unroll
                    for (int d=0;d<3;d++){
                        a8[0+d]  += acc0[nf*4+0]*Fp0[fb+u*3+d];
                        a8[3+d]  += acc0[nf*4+1]*Fp0[fb+u*3+d];
                        a8[6+d]  += acc0[nf*4+2]*Fp1[fb+u*3+d];
                        a8[9+d]  += acc0[nf*4+3]*Fp1[fb+u*3+d];
                        a8[12+d] += acc1[nf*4+0]*Fp2[fb+u*3+d];
                        a8[15+d] += acc1[nf*4+1]*Fp2[fb+u*3+d];
                        a8[18+d] += acc1[nf*4+2]*Fp3[fb+u*3+d];
                        a8[21+d] += acc1[nf*4+3]*Fp3[fb+u*3+d];
                    }
                }
            }
        }

        /* flushes */
        if (c == 3){
            red2(&g_aggs[cn0*24 + tq],     m0[0]*C_SC,  m0[1]*C_SC);
            red2(&g_aggs[cn0*24 + 8 + tq], m0[2]*C_SC,  m0[3]*C_SC);
            red2(&g_aggs[cn1*24 + tq],     m0[4]*C_SC,  m0[5]*C_SC);
            red2(&g_aggs[cn1*24 + 8 + tq], m0[6]*C_SC,  m0[7]*C_SC);
            red2(&g_aggs[cn2*24 + tq],     m0[8]*C_SC,  m0[9]*C_SC);
            red2(&g_aggs[cn2*24 + 8 + tq], m0[10]*C_SC, m0[11]*C_SC);
            red2(&g_aggs[cn3*24 + tq],     m0[12]*C_SC, m0[13]*C_SC);
            red2(&g_aggs[cn3*24 + 8 + tq], m0[14]*C_SC, m0[15]*C_SC);
        } else if (c == 7){
            const float* Fs[4] = {Fp0, Fp1, Fp2, Fp3};
            int cns[4] = {cn0, cn1, cn2, cn3};
#pragma unroll
            for (int E=0;E<4;E++){
#pragma unroll
                for (int s=0;s<4;s++){
                    int t = (s>>1)*8 + tq + (s&1);
                    float f = m1[E*4+s]*C_SC;
                    red4(&g_aggv[cns[E]*128 + t*4], f*Fs[E][72], f*Fs[E][73], f*Fs[E][74]);
                }
            }
        } else if (c == 8){
            int cns[4] = {cn0, cn1, cn2, cn3};
#pragma unroll
            for (int E=0;E<4;E++){
                red4(&g_aggv[cns[E]*128 + (16+tq)*4],   a8[E*6+0]*C_V0, a8[E*6+1]*C_V0, a8[E*6+2]*C_V0);
                red4(&g_aggv[cns[E]*128 + (16+tq+1)*4], a8[E*6+3]*C_V0, a8[E*6+4]*C_V0, a8[E*6+5]*C_V0);
            }
        } else if (c == 9){
            red2(&g_aggs[cn0*24 + 16 + tq], a9[0]*C_CG, a9[1]*C_CG);
            red2(&g_aggs[cn1*24 + 16 + tq], a9[2]*C_CG, a9[3]*C_CG);
            red2(&g_aggs[cn2*24 + 16 + tq], a9[4]*C_CG, a9[5]*C_CG);
            red2(&g_aggs[cn3*24 + 16 + tq], a9[6]*C_CG, a9[7]*C_CG);
        } else if (c == 10){
            int cns[4] = {cn0, cn1, cn2, cn3};
#pragma unroll
            for (int E=0;E<4;E++){
                red4(&g_aggv[cns[E]*128 + (24+tq)*4],   a8[E*6+0]*C_CG, a8[E*6+1]*C_CG, a8[E*6+2]*C_CG);
                red4(&g_aggv[cns[E]*128 + (24+tq+1)*4], a8[E*6+3]*C_CG, a8[E*6+4]*C_CG, a8[E*6+5]*C_CG);
            }
        }
    }
}

/* ---------------- fused node update: blocks 0..624 = s, 625..937 = v ---------------- */
#define SBLK 625
__global__ void upd_kernel(int l, const float* __restrict__ lws, const float* __restrict__ lwv){
    int tid = threadIdx.x;
    if (blockIdx.x < SBLK){
        int idx = blockIdx.x*256 + tid;
        int n = idx>>4, t = idx&15;
        float a = 0.f;
#pragma unroll
        for (int u=0;u<24;u++) a += g_aggs[n*24+u]*lws[l*384+u*16+t];
        __syncthreads();
        g_s[idx] += a*I24;
        float4* z4 = (float4*)(g_aggs + (size_t)blockIdx.x*384);
        if (tid < 96) z4[tid] = make_float4(0.f,0.f,0.f,0.f);
    } else {
        int vb = blockIdx.x - SBLK;
        int idx = vb*256 + tid;
        bool act = idx < NN*8;
        int n = act ? (idx>>3) : 0, w = idx&7;
        float ax=0.f, ay=0.f, az=0.f;
        if (act){
            const float4* av = (const float4*)(g_aggv + (size_t)n*128);
#pragma unroll
            for (int u=0;u<32;u++){
                float lw = lwv[l*256+u*8+w];
                float4 a4 = av[u];
                ax += a4.x*lw; ay += a4.y*lw; az += a4.z*lw;
            }
        }
        __syncthreads();
        if (act){
            g_v[n*24+w*3+0] += ax*I32;
            g_v[n*24+w*3+1] += ay*I32;
            g_v[n*24+w*3+2] += az*I32;
        }
        size_t base4 = (size_t)vb*1024;
        float4* z4 = (float4*)g_aggv;
        float4 z = make_float4(0.f,0.f,0.f,0.f);
#pragma unroll
        for (int i=0;i<4;i++){
            size_t gi = base4 + tid + i*256;
            if (gi < (size_t)NN*32) z4[gi] = z;
        }
    }
}

/* ---------------- output ---------------- */
__global__ void out_kernel(const float* __restrict__ ow, float* __restrict__ out){
    int idx = blockIdx.x*256 + threadIdx.x;
    if (idx >= NN*8) return;
    int n = idx>>3, t = idx&7;
    float a = 0.f;
#pragma unroll
    for (int k=0;k<16;k++) a += g_s[n*16+k]*ow[k*8+t];
    out[idx] = a*I16;
}

/* ---------------- launch ---------------- */
extern "C" void kernel_launch(void* const* d_in, const int* in_sizes, int n_in,
                              void* d_out, int out_size){
    const float *x=0, *pos=0, *embed_w=0, *radial_w=0, *radial_b=0;
    const float *fc_w=0, *fc_b=0, *lin_ws=0, *lin_wv=0, *out_w=0;
    const int *ei=0;
    for (int i=0;i<n_in;i++){
        switch (in_sizes[i]){
            case 80000:  x=(const float*)d_in[i]; break;
            case 30000:  pos=(const float*)d_in[i]; break;
            case 4000:   radial_w=(const float*)d_in[i]; break;
            case 400:    radial_b=(const float*)d_in[i]; break;
            case 281600: fc_w=(const float*)d_in[i]; break;
            case 2816:   fc_b=(const float*)d_in[i]; break;
            case 1536:   lin_ws=(const float*)d_in[i]; break;
            case 1024:   lin_wv=(const float*)d_in[i]; break;
            case 320000: ei=(const int*)d_in[i]; break;
            case 128:
                if (!embed_w) embed_w=(const float*)d_in[i];
                else          out_w=(const float*)d_in[i];
                break;
        }
    }
    const int* row = ei;
    const int* col = ei + NE;
    float* out = (float*)d_out;

    cudaFuncSetAttribute(msg_kernel, cudaFuncAttributeMaxDynamicSharedMemorySize, SM_TOT);

    conv_frag<<<4*NCH, 128>>>(fc_w, fc_b);
    conv_rwt<<<(4*RN*12 + 255)/256, 256>>>(radial_w, radial_b);
    geom_kernel<<<(NE+255)/256, 256>>>(pos, row, col);
    init_kernel<<<(NN*16+255)/256, 256>>>(x, embed_w);

    for (int l=0;l<4;l++){
        msg_kernel<<<NE/EB, 128, SM_TOT>>>(l, row, col);
        upd_kernel<<<SBLK + (NN*8 + 255)/256, 256>>>(l, lin_ws, lin_wv);
    }
    out_kernel<<<(NN*8+255)/256, 256>>>(out_w, out);
}

// round 15
// speedup vs baseline: 1.1403x; 1.1403x over previous
#include <cuda_runtime.h>
#include <cuda_fp16.h>
#include <math.h>
#include <stdint.h>

#define NN 10000
#define NE 160000
#define NB 10
#define RN 100
#define WN 704
#define NCH 11
#define EB 128
#define KG 128
#define HS 130        /* hh row stride in halves (conflict-free) */

#define SQ3    1.7320508075688772f
#define ISQ3   0.5773502691896258f
#define SQ75   2.7386127875258306f
#define C_SC   0.25f
#define C_V0   0.35355339059327373f
#define C_CG   0.20412414523193152f
#define I24    0.20412414523193152f
#define I32    0.17677669529663687f
#define I8     0.35355339059327373f
#define I16    0.25f
#define THIRD  0.3333333333333333f

__device__ float g_rbf[NE*NB];
__device__ float g_sh1[NE*3];
__device__ float g_s[NN*16];
__device__ float g_v[NN*24];
__device__ float g_aggs[NN*24];
__device__ float g_aggv[NN*128];     /* [N][32][4] for float4 atomics */
__device__ uint16_t g_bt[4*WN*KG];   /* fc_w^T fp16, [l][n][k] padded */
__device__ float g_rwT[4*RN*12];     /* radial w transposed: [l][r][10 w + bias + pad] */

/* ---- smem layout (bytes) ----
   UNION @0: hh (128*130*2 = 33280) overlaid with feat (128*77*4 = 39424)
   COL   @39424 (512)
   B     @39936 (2 x 16384)                                              */
#define OFF_U    0
#define OFF_COL  39424
#define OFF_B    39936
#define SM_TOT   72704
#define FST 77

__device__ __forceinline__ uint32_t smem_u32(const void* p){
    uint32_t a; asm("{ .reg .u64 t; cvta.to.shared.u64 t, %1; cvt.u32.u64 %0, t; }":"=r"(a):"l"(p)); return a;
}
__device__ __forceinline__ void cpa16(uint32_t dst, const void* src){
    asm volatile("cp.async.ca.shared.global [%0], [%1], 16;"::"r"(dst),"l"(src):"memory");
}
__device__ __forceinline__ void cp_commit(){ asm volatile("cp.async.commit_group;":::"memory"); }
__device__ __forceinline__ void cp_wait0(){ asm volatile("cp.async.wait_group 0;":::"memory"); }
__device__ __forceinline__ void ldsm4(uint32_t* r, uint32_t a){
    asm volatile("ldmatrix.sync.aligned.m8n8.x4.shared.b16 {%0,%1,%2,%3}, [%4];"
        :"=r"(r[0]),"=r"(r[1]),"=r"(r[2]),"=r"(r[3]):"r"(a));
}
__device__ __forceinline__ void mma16816(float* d, const uint32_t* a, uint32_t b0, uint32_t b1){
    asm volatile("mma.sync.aligned.m16n8k16.row.col.f32.f16.f16.f32 "
        "{%0,%1,%2,%3}, {%4,%5,%6,%7}, {%8,%9}, {%0,%1,%2,%3};"
        : "+f"(d[0]),"+f"(d[1]),"+f"(d[2]),"+f"(d[3])
        : "r"(a[0]),"r"(a[1]),"r"(a[2]),"r"(a[3]),"r"(b0),"r"(b1));
}
__device__ __forceinline__ void red2(float* p, float a, float b){
    atomicAdd((float2*)p, make_float2(a,b));
}
__device__ __forceinline__ void red4(float* p, float a, float b, float c){
    atomicAdd((float4*)p, make_float4(a,b,c,0.f));
}

/* ---------------- fused prologue: geom | s-init | zeroing | rw transpose ---------------- */
__global__ void prol_kernel(const float* __restrict__ pos,
                            const int* __restrict__ row, const int* __restrict__ col,
                            const float* __restrict__ x, const float* __restrict__ ew,
                            const float* __restrict__ rw, const float* __restrict__ rb){
    int b = blockIdx.x, t = threadIdx.x;
    int gid = b*256 + t;

    if (b < 625){
        /* geometry: e = gid, exactly NE = 625*256 */
        int e = gid;
        int r = row[e], c = col[e];
        float vx = pos[3*r]-pos[3*c], vy = pos[3*r+1]-pos[3*c+1], vz = pos[3*r+2]-pos[3*c+2];
        float len = sqrtf(vx*vx+vy*vy+vz*vz+1e-12f);
        float inv = 1.0f/len;
        g_sh1[3*e]=SQ3*vx*inv; g_sh1[3*e+1]=SQ3*vy*inv; g_sh1[3*e+2]=SQ3*vz*inv;
        const float step = 10.0f/9.0f;
#pragma unroll
        for (int k=0;k<NB;k++){ float d = len - (float)k*step; g_rbf[e*NB+k] = expf(-0.405f*d*d); }
    } else {
        /* s init: idx over exactly NN*16 = 625*256 */
        int idx = (b-625)*256 + t;
        int n = idx>>4, tt = idx&15;
        float a = 0.f;
#pragma unroll
        for (int k=0;k<8;k++) a += x[n*8+k]*ew[k*16+tt];
        g_s[idx] = a*I8;
    }

    /* grid-stride float4 zeroing: aggs 60000 | v 60000 | aggv 320000 */
    float4 z = make_float4(0.f,0.f,0.f,0.f);
    for (int i = gid; i < 440000; i += 320000){
        if (i < 60000)        ((float4*)g_aggs)[i] = z;
        else if (i < 120000)  ((float4*)g_v)[i-60000] = z;
        else                  ((float4*)g_aggv)[i-120000] = z;
    }
    /* radial transpose: 4800 entries */
    if (gid < 4800){
        int j = gid % 12, r = (gid/12) % RN, l = gid / (RN*12);
        float v = 0.f;
        if (j < 10)       v = rw[l*1000 + j*100 + r];
        else if (j == 10) v = rb[l*100 + r];
        g_rwT[gid] = v;
    }
}

/* ---------------- one-time fc_w -> BT fp16 (padded K=128) ---------------- */
__global__ void conv_fcw(const float* __restrict__ fcw, const float* __restrict__ fcb){
    int idx = blockIdx.x*256 + threadIdx.x;
    if (idx >= 4*WN*KG) return;
    int k = idx & (KG-1);
    int n = (idx >> 7) % WN;
    int l = idx / (WN*KG);
    float v = 0.f;
    if (k < 100)       v = fcw[(size_t)(l*RN + k)*WN + n];
    else if (k == 100) v = fcb[l*WN + n];
    __half h = __float2half_rn(v);
    g_bt[idx] = *(uint16_t*)&h;
}

/* ---------------- fused HMMA message kernel: 4 warps, Tm=32 ---------------- */
__global__ void __launch_bounds__(128, 3)
msg_kernel(int l, const int* __restrict__ row, const int* __restrict__ col){
    extern __shared__ char smem[];
    uint32_t sbase = smem_u32(smem);
    int tid = threadIdx.x;
    int wid = tid>>5, lane = tid&31;
    int g = lane>>2, tig = lane&3;
    int mi = lane>>3, rowin = lane&7;
    int tq = tig*2;
    int e0 = blockIdx.x*EB;

    uint16_t* hh = (uint16_t*)(smem + OFF_U);
    float*    featf = (float*)(smem + OFF_U);
    int*      colsm = (int*)(smem + OFF_COL);

    /* stage B chunk 0 (1024 x 16B, 128 threads) */
    {
        const uint16_t* src = g_bt + (size_t)l*WN*KG;
#pragma unroll
        for (int i=0;i<8;i++){
            int cid = tid + i*128;
            int n = cid>>4, j = cid&15;
            cpa16(sbase + OFF_B + ((n*16 + (j ^ (n&7)))<<4), src + (size_t)n*KG + j*8);
        }
        cp_commit();
    }

    /* h compute: thread = edge, broadcast float4 LDG weights */
    {
        int eg = e0 + tid;
        float rbf[NB];
        const float2* rb2 = (const float2*)(g_rbf + (size_t)eg*NB);
#pragma unroll
        for (int i=0;i<5;i++){ float2 v = rb2[i]; rbf[i*2]=v.x; rbf[i*2+1]=v.y; }
        const float4* wt = (const float4*)(g_rwT + l*RN*12);
        uint16_t* hrow = hh + tid*HS;
#pragma unroll 4
        for (int r=0;r<RN;r++){
            float4 c0 = wt[r*3], c1 = wt[r*3+1], c2 = wt[r*3+2];
            float a = c2.z
                + rbf[0]*c0.x + rbf[1]*c0.y + rbf[2]*c0.z + rbf[3]*c0.w
                + rbf[4]*c1.x + rbf[5]*c1.y + rbf[6]*c1.z + rbf[7]*c1.w
                + rbf[8]*c2.x + rbf[9]*c2.y;
            a = fmaxf(a, 0.f);
            __half hv = __float2half_rn(a);
            hrow[r] = *(uint16_t*)&hv;
        }
        hrow[100] = 0x3C00;                 /* bias row: A = 1.0 */
#pragma unroll
        for (int r=101;r<112;r++) hrow[r] = 0;
    }
    __syncthreads();

    /* A fragment preload: warp strip = 32 edges (rows r0,+8 and r0+16,+24) */
    uint32_t A0[28], A1[28];
    int r0 = wid*32 + g;
    {
#pragma unroll
        for (int ks=0;ks<7;ks++){
            int k0 = ks*16 + tq;
            A0[ks*4+0] = *(uint32_t*)&hh[r0*HS + k0];
            A0[ks*4+1] = *(uint32_t*)&hh[(r0+8)*HS + k0];
            A0[ks*4+2] = *(uint32_t*)&hh[r0*HS + k0+8];
            A0[ks*4+3] = *(uint32_t*)&hh[(r0+8)*HS + k0+8];
            A1[ks*4+0] = *(uint32_t*)&hh[(r0+16)*HS + k0];
            A1[ks*4+1] = *(uint32_t*)&hh[(r0+24)*HS + k0];
            A1[ks*4+2] = *(uint32_t*)&hh[(r0+16)*HS + k0+8];
            A1[ks*4+3] = *(uint32_t*)&hh[(r0+24)*HS + k0+8];
        }
    }
    __syncthreads();   /* hh dead; feat overlays */

    /* features + col: thread = edge */
    {
        int e = tid, eg = e0 + e;
        int rr = row[eg];
        colsm[e] = col[eg];
        float* F = featf + e*FST;
#pragma unroll
        for (int t=0;t<16;t++) F[t] = g_s[rr*16+t];
#pragma unroll
        for (int i=0;i<24;i++) F[16+i] = g_v[rr*24+i];
        float s1x = g_sh1[eg*3], s1y = g_sh1[eg*3+1], s1z = g_sh1[eg*3+2];
        F[72]=s1x; F[73]=s1y; F[74]=s1z;
        float ux=s1x*ISQ3, uy=s1y*ISQ3, uz=s1z*ISQ3;
#pragma unroll
        for (int u=0;u<8;u++){
            float vx=F[16+u*3], vy=F[17+u*3], vz=F[18+u*3];
            float dot = ux*vx+uy*vy+uz*vz;
            F[40+u] = SQ3*dot;
            F[48+u*3] = SQ75*(dot*ux - vx*THIRD);
            F[49+u*3] = SQ75*(dot*uy - vy*THIRD);
            F[50+u*3] = SQ75*(dot*uz - vz*THIRD);
        }
    }
    cp_wait0();
    __syncthreads();

    const float* Fp0 = featf + r0*FST;
    const float* Fp1 = featf + (r0+8)*FST;
    const float* Fp2 = featf + (r0+16)*FST;
    const float* Fp3 = featf + (r0+24)*FST;
    int cn0 = colsm[r0], cn1 = colsm[r0+8], cn2 = colsm[r0+16], cn3 = colsm[r0+24];
    float m0[16], m1[16];

#pragma unroll
    for (int c=0;c<NCH;c++){
        if (c+1 < NCH){
            const uint16_t* src = g_bt + ((size_t)l*WN + (c+1)*64)*KG;
            uint32_t db = sbase + OFF_B + ((c+1)&1)*16384;
#pragma unroll
            for (int i=0;i<8;i++){
                int cid = tid + i*128;
                int n = cid>>4, j = cid&15;
                cpa16(db + ((n*16 + (j ^ (n&7)))<<4), src + (size_t)n*KG + j*8);
            }
            cp_commit();
        }

        float a8[24];
        float a9[8];
        if (c >= 8){
#pragma unroll
            for (int i=0;i<24;i++) a8[i]=0.f;
#pragma unroll
            for (int i=0;i<8;i++)  a9[i]=0.f;
        }
        if (c == 0){
#pragma unroll
            for (int i=0;i<16;i++) m0[i]=0.f;
        }
        if (c == 4){
#pragma unroll
            for (int i=0;i<16;i++) m1[i]=0.f;
        }

        uint32_t bb = sbase + OFF_B + (c&1)*16384;
#pragma unroll
        for (int p=0;p<2;p++){
            /* GEMM half-pass: nf = p*4+nf', both M-tiles share B-frags */
            float acc0[16], acc1[16];
#pragma unroll
            for (int i=0;i<16;i++){ acc0[i]=0.f; acc1[i]=0.f; }
#pragma unroll
            for (int q4=0;q4<4;q4++){
#pragma unroll
                for (int nf=0;nf<4;nf++){
                    int nfg = p*4 + nf;
                    uint32_t bm[4];
                    ldsm4(bm, bb + (((nfg*8 + rowin)*16 + ((q4*4+mi) ^ rowin)) << 4));
                    mma16816(acc0 + nf*4, A0 + (2*q4)*4, bm[0], bm[1]);
                    mma16816(acc1 + nf*4, A1 + (2*q4)*4, bm[0], bm[1]);
                    if (q4 < 3){
                        mma16816(acc0 + nf*4, A0 + (2*q4+1)*4, bm[2], bm[3]);
                        mma16816(acc1 + nf*4, A1 + (2*q4+1)*4, bm[2], bm[3]);
                    }
                }
            }
            /* consume pass */
            if (c < 4){
#pragma unroll
                for (int nf=0;nf<4;nf++){
                    int u = c*4 + p*2 + (nf>>1);
                    int sl = (nf&1)*2;
                    float s0 = Fp0[u], s1 = Fp1[u], s2 = Fp2[u], s3 = Fp3[u];
                    m0[sl+0]  += acc0[nf*4+0]*s0;  m0[sl+1]  += acc0[nf*4+1]*s0;
                    m0[4+sl]  += acc0[nf*4+2]*s1;  m0[5+sl]  += acc0[nf*4+3]*s1;
                    m0[8+sl]  += acc1[nf*4+0]*s2;  m0[9+sl]  += acc1[nf*4+1]*s2;
                    m0[12+sl] += acc1[nf*4+2]*s3;  m0[13+sl] += acc1[nf*4+3]*s3;
                }
            } else if (c < 8){
#pragma unroll
                for (int nf=0;nf<4;nf++){
                    int u = (c-4)*4 + p*2 + (nf>>1);
                    int sl = (nf&1)*2;
                    float s0 = Fp0[u], s1 = Fp1[u], s2 = Fp2[u], s3 = Fp3[u];
                    m1[sl+0]  += acc0[nf*4+0]*s0;  m1[sl+1]  += acc0[nf*4+1]*s0;
                    m1[4+sl]  += acc0[nf*4+2]*s1;  m1[5+sl]  += acc0[nf*4+3]*s1;
                    m1[8+sl]  += acc1[nf*4+0]*s2;  m1[9+sl]  += acc1[nf*4+1]*s2;
                    m1[12+sl] += acc1[nf*4+2]*s3;  m1[13+sl] += acc1[nf*4+3]*s3;
                }
            } else if (c == 9){
#pragma unroll
                for (int nf=0;nf<4;nf++){
                    int u = p*4 + nf;
                    a9[0] += acc0[nf*4+0]*Fp0[40+u];  a9[1] += acc0[nf*4+1]*Fp0[40+u];
                    a9[2] += acc0[nf*4+2]*Fp1[40+u];  a9[3] += acc0[nf*4+3]*Fp1[40+u];
                    a9[4] += acc1[nf*4+0]*Fp2[40+u];  a9[5] += acc1[nf*4+1]*Fp2[40+u];
                    a9[6] += acc1[nf*4+2]*Fp3[40+u];  a9[7] += acc1[nf*4+3]*Fp3[40+u];
                }
            } else {  /* c==8 or c==10 */
                int fb = (c==8) ? 16 : 48;
#pragma unroll
                for (int nf=0;nf<4;nf++){
                    int u = p*4 + nf;
#pragma unroll
                    for (int d=0;d<3;d++){
                        a8[0+d]  += acc0[nf*4+0]*Fp0[fb+u*3+d];
                        a8[3+d]  += acc0[nf*4+1]*Fp0[fb+u*3+d];
                        a8[6+d]  += acc0[nf*4+2]*Fp1[fb+u*3+d];
                        a8[9+d]  += acc0[nf*4+3]*Fp1[fb+u*3+d];
                        a8[12+d] += acc1[nf*4+0]*Fp2[fb+u*3+d];
                        a8[15+d] += acc1[nf*4+1]*Fp2[fb+u*3+d];
                        a8[18+d] += acc1[nf*4+2]*Fp3[fb+u*3+d];
                        a8[21+d] += acc1[nf*4+3]*Fp3[fb+u*3+d];
                    }
                }
            }
        }

        /* flushes */
        if (c == 3){
            red2(&g_aggs[cn0*24 + tq],     m0[0]*C_SC,  m0[1]*C_SC);
            red2(&g_aggs[cn0*24 + 8 + tq], m0[2]*C_SC,  m0[3]*C_SC);
            red2(&g_aggs[cn1*24 + tq],     m0[4]*C_SC,  m0[5]*C_SC);
            red2(&g_aggs[cn1*24 + 8 + tq], m0[6]*C_SC,  m0[7]*C_SC);
            red2(&g_aggs[cn2*24 + tq],     m0[8]*C_SC,  m0[9]*C_SC);
            red2(&g_aggs[cn2*24 + 8 + tq], m0[10]*C_SC, m0[11]*C_SC);
            red2(&g_aggs[cn3*24 + tq],     m0[12]*C_SC, m0[13]*C_SC);
            red2(&g_aggs[cn3*24 + 8 + tq], m0[14]*C_SC, m0[15]*C_SC);
        } else if (c == 7){
            const float* Fs[4] = {Fp0, Fp1, Fp2, Fp3};
            int cns[4] = {cn0, cn1, cn2, cn3};
#pragma unroll
            for (int E=0;E<4;E++){
#pragma unroll
                for (int s=0;s<4;s++){
                    int t = (s>>1)*8 + tq + (s&1);
                    float f = m1[E*4+s]*C_SC;
                    red4(&g_aggv[cns[E]*128 + t*4], f*Fs[E][72], f*Fs[E][73], f*Fs[E][74]);
                }
            }
        } else if (c == 8){
            int cns[4] = {cn0, cn1, cn2, cn3};
#pragma unroll
            for (int E=0;E<4;E++){
                red4(&g_aggv[cns[E]*128 + (16+tq)*4],   a8[E*6+0]*C_V0, a8[E*6+1]*C_V0, a8[E*6+2]*C_V0);
                red4(&g_aggv[cns[E]*128 + (16+tq+1)*4], a8[E*6+3]*C_V0, a8[E*6+4]*C_V0, a8[E*6+5]*C_V0);
            }
        } else if (c == 9){
            red2(&g_aggs[cn0*24 + 16 + tq], a9[0]*C_CG, a9[1]*C_CG);
            red2(&g_aggs[cn1*24 + 16 + tq], a9[2]*C_CG, a9[3]*C_CG);
            red2(&g_aggs[cn2*24 + 16 + tq], a9[4]*C_CG, a9[5]*C_CG);
            red2(&g_aggs[cn3*24 + 16 + tq], a9[6]*C_CG, a9[7]*C_CG);
        } else if (c == 10){
            int cns[4] = {cn0, cn1, cn2, cn3};
#pragma unroll
            for (int E=0;E<4;E++){
                red4(&g_aggv[cns[E]*128 + (24+tq)*4],   a8[E*6+0]*C_CG, a8[E*6+1]*C_CG, a8[E*6+2]*C_CG);
                red4(&g_aggv[cns[E]*128 + (24+tq+1)*4], a8[E*6+3]*C_CG, a8[E*6+4]*C_CG, a8[E*6+5]*C_CG);
            }
        }

        cp_wait0();
        __syncthreads();
    }
}

/* ---------------- fused node update: blocks 0..624 = s, 625..937 = v ---------------- */
#define SBLK 625
__global__ void upd_kernel(int l, const float* __restrict__ lws, const float* __restrict__ lwv){
    int tid = threadIdx.x;
    if (blockIdx.x < SBLK){
        /* s-update: 16 nodes per block */
        int idx = blockIdx.x*256 + tid;
        int n = idx>>4, t = idx&15;
        float a = 0.f;
#pragma unroll
        for (int u=0;u<24;u++) a += g_aggs[n*24+u]*lws[l*384+u*16+t];
        __syncthreads();
        g_s[idx] += a*I24;
        float4* z4 = (float4*)(g_aggs + (size_t)blockIdx.x*384);
        if (tid < 96) z4[tid] = make_float4(0.f,0.f,0.f,0.f);
    } else {
        /* v-update: 32 nodes per block */
        int vb = blockIdx.x - SBLK;
        int idx = vb*256 + tid;
        bool act = idx < NN*8;
        int n = act ? (idx>>3) : 0, w = idx&7;
        float ax=0.f, ay=0.f, az=0.f;
        if (act){
            const float4* av = (const float4*)(g_aggv + (size_t)n*128);
#pragma unroll
            for (int u=0;u<32;u++){
                float lw = lwv[l*256+u*8+w];
                float4 a4 = av[u];
                ax += a4.x*lw; ay += a4.y*lw; az += a4.z*lw;
            }
        }
        __syncthreads();
        if (act){
            g_v[n*24+w*3+0] += ax*I32;
            g_v[n*24+w*3+1] += ay*I32;
            g_v[n*24+w*3+2] += az*I32;
        }
        size_t base4 = (size_t)vb*1024;          /* 32 nodes * 128 floats = 1024 float4 */
        float4* z4 = (float4*)g_aggv;
        float4 z = make_float4(0.f,0.f,0.f,0.f);
#pragma unroll
        for (int i=0;i<4;i++){
            size_t gi = base4 + tid + i*256;
            if (gi < (size_t)NN*32) z4[gi] = z;
        }
    }
}

/* ---------------- output ---------------- */
__global__ void out_kernel(const float* __restrict__ ow, float* __restrict__ out){
    int idx = blockIdx.x*256 + threadIdx.x;
    if (idx >= NN*8) return;
    int n = idx>>3, t = idx&7;
    float a = 0.f;
#pragma unroll
    for (int k=0;k<16;k++) a += g_s[n*16+k]*ow[k*8+t];
    out[idx] = a*I16;
}

/* ---------------- launch ---------------- */
extern "C" void kernel_launch(void* const* d_in, const int* in_sizes, int n_in,
                              void* d_out, int out_size){
    const float *x=0, *pos=0, *embed_w=0, *radial_w=0, *radial_b=0;
    const float *fc_w=0, *fc_b=0, *lin_ws=0, *lin_wv=0, *out_w=0;
    const int *ei=0;
    for (int i=0;i<n_in;i++){
        switch (in_sizes[i]){
            case 80000:  x=(const float*)d_in[i]; break;
            case 30000:  pos=(const float*)d_in[i]; break;
            case 4000:   radial_w=(const float*)d_in[i]; break;
            case 400:    radial_b=(const float*)d_in[i]; break;
            case 281600: fc_w=(const float*)d_in[i]; break;
            case 2816:   fc_b=(const float*)d_in[i]; break;
            case 1536:   lin_ws=(const float*)d_in[i]; break;
            case 1024:   lin_wv=(const float*)d_in[i]; break;
            case 320000: ei=(const int*)d_in[i]; break;
            case 128:
                if (!embed_w) embed_w=(const float*)d_in[i];
                else          out_w=(const float*)d_in[i];
                break;
        }
    }
    const int* row = ei;
    const int* col = ei + NE;
    float* out = (float*)d_out;

    cudaFuncSetAttribute(msg_kernel, cudaFuncAttributeMaxDynamicSharedMemorySize, SM_TOT);

    conv_fcw<<<(4*WN*KG + 255)/256, 256>>>(fc_w, fc_b);
    prol_kernel<<<1250, 256>>>(pos, row, col, x, embed_w, radial_w, radial_b);

    for (int l=0;l<4;l++){
        msg_kernel<<<NE/EB, 128, SM_TOT>>>(l, row, col);
        upd_kernel<<<SBLK + (NN*8 + 255)/256, 256>>>(l, lin_ws, lin_wv);
    }
    out_kernel<<<(NN*8+255)/256, 256>>>(out_w, out);
}

// round 16
// speedup vs baseline: 1.2104x; 1.0615x over previous
#include <cuda_runtime.h>
#include <cuda_fp16.h>
#include <math.h>
#include <stdint.h>

#define NN 10000
#define NE 160000
#define NB 10
#define RN 100
#define WN 704
#define NCH 11
#define EB 128
#define KG 128
#define HS 130        /* hh row stride in halves (conflict-free) */

#define SQ3    1.7320508075688772f
#define ISQ3   0.5773502691896258f
#define SQ75   2.7386127875258306f
#define C_SC   0.25f
#define C_V0   0.35355339059327373f
#define C_CG   0.20412414523193152f
#define I24    0.20412414523193152f
#define I32    0.17677669529663687f
#define I8     0.35355339059327373f
#define I16    0.25f
#define THIRD  0.3333333333333333f

__device__ float g_rbf[NE*NB];
__device__ float g_sh1[NE*3];
__device__ float g_s[NN*16];
__device__ float g_v[NN*24];
__device__ float g_aggs[NN*24];
__device__ float g_aggv[NN*128];     /* [N][32][4] for float4 atomics */
__device__ uint16_t g_bt[4*WN*KG];   /* fc_w^T fp16, [l][n][k] padded */
__device__ float g_rwT[4*RN*12];     /* radial w transposed: [l][r][10 w + bias + pad] */

/* ---- smem layout (bytes) ----
   UNION @0: hh (128*130*2 = 33280) overlaid with feat (128*77*4 = 39424)
   COL   @39424 (512)
   B     @39936 (2 x 16384)                                              */
#define OFF_U    0
#define OFF_COL  39424
#define OFF_B    39936
#define SM_TOT   72704
#define FST 77

__device__ __forceinline__ uint32_t smem_u32(const void* p){
    uint32_t a; asm("{ .reg .u64 t; cvta.to.shared.u64 t, %1; cvt.u32.u64 %0, t; }":"=r"(a):"l"(p)); return a;
}
__device__ __forceinline__ void cpa16(uint32_t dst, const void* src){
    asm volatile("cp.async.ca.shared.global [%0], [%1], 16;"::"r"(dst),"l"(src):"memory");
}
__device__ __forceinline__ void cp_commit(){ asm volatile("cp.async.commit_group;":::"memory"); }
__device__ __forceinline__ void cp_wait0(){ asm volatile("cp.async.wait_group 0;":::"memory"); }
__device__ __forceinline__ void ldsm4(uint32_t* r, uint32_t a){
    asm volatile("ldmatrix.sync.aligned.m8n8.x4.shared.b16 {%0,%1,%2,%3}, [%4];"
        :"=r"(r[0]),"=r"(r[1]),"=r"(r[2]),"=r"(r[3]):"r"(a));
}
__device__ __forceinline__ void mma16816(float* d, const uint32_t* a, uint32_t b0, uint32_t b1){
    asm volatile("mma.sync.aligned.m16n8k16.row.col.f32.f16.f16.f32 "
        "{%0,%1,%2,%3}, {%4,%5,%6,%7}, {%8,%9}, {%0,%1,%2,%3};"
        : "+f"(d[0]),"+f"(d[1]),"+f"(d[2]),"+f"(d[3])
        : "r"(a[0]),"r"(a[1]),"r"(a[2]),"r"(a[3]),"r"(b0),"r"(b1));
}
__device__ __forceinline__ void red2(float* p, float a, float b){
    atomicAdd((float2*)p, make_float2(a,b));
}
__device__ __forceinline__ void red4(float* p, float a, float b, float c){
    atomicAdd((float4*)p, make_float4(a,b,c,0.f));
}

/* ---------------- fused prologue: geom | s-init | zeroing | rw transpose ---------------- */
__global__ void prol_kernel(const float* __restrict__ pos,
                            const int* __restrict__ row, const int* __restrict__ col,
                            const float* __restrict__ x, const float* __restrict__ ew,
                            const float* __restrict__ rw, const float* __restrict__ rb){
    int b = blockIdx.x, t = threadIdx.x;
    int gid = b*256 + t;

    if (b < 625){
        int e = gid;
        int r = row[e], c = col[e];
        float vx = pos[3*r]-pos[3*c], vy = pos[3*r+1]-pos[3*c+1], vz = pos[3*r+2]-pos[3*c+2];
        float len = sqrtf(vx*vx+vy*vy+vz*vz+1e-12f);
        float inv = 1.0f/len;
        g_sh1[3*e]=SQ3*vx*inv; g_sh1[3*e+1]=SQ3*vy*inv; g_sh1[3*e+2]=SQ3*vz*inv;
        const float step = 10.0f/9.0f;
#pragma unroll
        for (int k=0;k<NB;k++){ float d = len - (float)k*step; g_rbf[e*NB+k] = expf(-0.405f*d*d); }
    } else {
        int idx = (b-625)*256 + t;
        int n = idx>>4, tt = idx&15;
        float a = 0.f;
#pragma unroll
        for (int k=0;k<8;k++) a += x[n*8+k]*ew[k*16+tt];
        g_s[idx] = a*I8;
    }

    float4 z = make_float4(0.f,0.f,0.f,0.f);
    for (int i = gid; i < 440000; i += 320000){
        if (i < 60000)        ((float4*)g_aggs)[i] = z;
        else if (i < 120000)  ((float4*)g_v)[i-60000] = z;
        else                  ((float4*)g_aggv)[i-120000] = z;
    }
    if (gid < 4800){
        int j = gid % 12, r = (gid/12) % RN, l = gid / (RN*12);
        float v = 0.f;
        if (j < 10)       v = rw[l*1000 + j*100 + r];
        else if (j == 10) v = rb[l*100 + r];
        g_rwT[gid] = v;
    }
}

/* ---------------- one-time fc_w -> BT fp16 (padded K=128) ---------------- */
__global__ void conv_fcw(const float* __restrict__ fcw, const float* __restrict__ fcb){
    int idx = blockIdx.x*256 + threadIdx.x;
    if (idx >= 4*WN*KG) return;
    int k = idx & (KG-1);
    int n = (idx >> 7) % WN;
    int l = idx / (WN*KG);
    float v = 0.f;
    if (k < 100)       v = fcw[(size_t)(l*RN + k)*WN + n];
    else if (k == 100) v = fcb[l*WN + n];
    __half h = __float2half_rn(v);
    g_bt[idx] = *(uint16_t*)&h;
}

/* ---------------- fused HMMA message kernel: 4 warps, Tm=32 ---------------- */
__global__ void __launch_bounds__(128, 3)
msg_kernel(int l, const int* __restrict__ row, const int* __restrict__ col){
    extern __shared__ char smem[];
    uint32_t sbase = smem_u32(smem);
    int tid = threadIdx.x;
    int wid = tid>>5, lane = tid&31;
    int g = lane>>2, tig = lane&3;
    int mi = lane>>3, rowin = lane&7;
    int tq = tig*2;
    int e0 = blockIdx.x*EB;

    uint16_t* hh = (uint16_t*)(smem + OFF_U);
    float*    featf = (float*)(smem + OFF_U);
    int*      colsm = (int*)(smem + OFF_COL);

    /* stage B chunk 0 (1024 x 16B, 128 threads) */
    {
        const uint16_t* src = g_bt + (size_t)l*WN*KG;
#pragma unroll
        for (int i=0;i<8;i++){
            int cid = tid + i*128;
            int n = cid>>4, j = cid&15;
            cpa16(sbase + OFF_B + ((n*16 + (j ^ (n&7)))<<4), src + (size_t)n*KG + j*8);
        }
        cp_commit();
    }

    /* h compute: thread = edge, broadcast float4 LDG weights */
    {
        int eg = e0 + tid;
        float rbf[NB];
        const float2* rb2 = (const float2*)(g_rbf + (size_t)eg*NB);
#pragma unroll
        for (int i=0;i<5;i++){ float2 v = rb2[i]; rbf[i*2]=v.x; rbf[i*2+1]=v.y; }
        const float4* wt = (const float4*)(g_rwT + l*RN*12);
        uint16_t* hrow = hh + tid*HS;
#pragma unroll 4
        for (int r=0;r<RN;r++){
            float4 c0 = wt[r*3], c1 = wt[r*3+1], c2 = wt[r*3+2];
            float a = c2.z
                + rbf[0]*c0.x + rbf[1]*c0.y + rbf[2]*c0.z + rbf[3]*c0.w
                + rbf[4]*c1.x + rbf[5]*c1.y + rbf[6]*c1.z + rbf[7]*c1.w
                + rbf[8]*c2.x + rbf[9]*c2.y;
            a = fmaxf(a, 0.f);
            __half hv = __float2half_rn(a);
            hrow[r] = *(uint16_t*)&hv;
        }
        hrow[100] = 0x3C00;                 /* bias row: A = 1.0 */
#pragma unroll
        for (int r=101;r<112;r++) hrow[r] = 0;
    }
    __syncthreads();

    /* A fragment preload: warp strip = 32 edges (rows r0,+8 and r0+16,+24) */
    uint32_t A0[28], A1[28];
    int r0 = wid*32 + g;
    {
#pragma unroll
        for (int ks=0;ks<7;ks++){
            int k0 = ks*16 + tq;
            A0[ks*4+0] = *(uint32_t*)&hh[r0*HS + k0];
            A0[ks*4+1] = *(uint32_t*)&hh[(r0+8)*HS + k0];
            A0[ks*4+2] = *(uint32_t*)&hh[r0*HS + k0+8];
            A0[ks*4+3] = *(uint32_t*)&hh[(r0+8)*HS + k0+8];
            A1[ks*4+0] = *(uint32_t*)&hh[(r0+16)*HS + k0];
            A1[ks*4+1] = *(uint32_t*)&hh[(r0+24)*HS + k0];
            A1[ks*4+2] = *(uint32_t*)&hh[(r0+16)*HS + k0+8];
            A1[ks*4+3] = *(uint32_t*)&hh[(r0+24)*HS + k0+8];
        }
    }
    __syncthreads();   /* hh dead; feat overlays */

    /* features + col: thread = edge (vectorized gathers) */
    {
        int e = tid, eg = e0 + e;
        int rr = row[eg];
        colsm[e] = col[eg];
        float* F = featf + e*FST;
        {   /* g_s: 16 floats = 4 float4 (64B-aligned per node) */
            const float4* s4 = (const float4*)(g_s + (size_t)rr*16);
#pragma unroll
            for (int i=0;i<4;i++){
                float4 v = s4[i];
                F[i*4+0]=v.x; F[i*4+1]=v.y; F[i*4+2]=v.z; F[i*4+3]=v.w;
            }
        }
        {   /* g_v: 24 floats = 6 float4 (96B stride, 16B-aligned) */
            const float4* v4 = (const float4*)(g_v + (size_t)rr*24);
#pragma unroll
            for (int i=0;i<6;i++){
                float4 v = v4[i];
                F[16+i*4+0]=v.x; F[16+i*4+1]=v.y; F[16+i*4+2]=v.z; F[16+i*4+3]=v.w;
            }
        }
        float s1x = g_sh1[eg*3], s1y = g_sh1[eg*3+1], s1z = g_sh1[eg*3+2];
        F[72]=s1x; F[73]=s1y; F[74]=s1z;
        float ux=s1x*ISQ3, uy=s1y*ISQ3, uz=s1z*ISQ3;
#pragma unroll
        for (int u=0;u<8;u++){
            float vx=F[16+u*3], vy=F[17+u*3], vz=F[18+u*3];
            float dot = ux*vx+uy*vy+uz*vz;
            F[40+u] = SQ3*dot;
            F[48+u*3] = SQ75*(dot*ux - vx*THIRD);
            F[49+u*3] = SQ75*(dot*uy - vy*THIRD);
            F[50+u*3] = SQ75*(dot*uz - vz*THIRD);
        }
    }
    cp_wait0();
    __syncthreads();

    const float* Fp0 = featf + r0*FST;
    const float* Fp1 = featf + (r0+8)*FST;
    const float* Fp2 = featf + (r0+16)*FST;
    const float* Fp3 = featf + (r0+24)*FST;
    int cn0 = colsm[r0], cn1 = colsm[r0+8], cn2 = colsm[r0+16], cn3 = colsm[r0+24];
    float m0[16], m1[16];

#pragma unroll
    for (int c=0;c<NCH;c++){
        if (c+1 < NCH){
            const uint16_t* src = g_bt + ((size_t)l*WN + (c+1)*64)*KG;
            uint32_t db = sbase + OFF_B + ((c+1)&1)*16384;
#pragma unroll
            for (int i=0;i<8;i++){
                int cid = tid + i*128;
                int n = cid>>4, j = cid&15;
                cpa16(db + ((n*16 + (j ^ (n&7)))<<4), src + (size_t)n*KG + j*8);
            }
            cp_commit();
        }

        float a8[24];
        float a9[8];
        if (c >= 8){
#pragma unroll
            for (int i=0;i<24;i++) a8[i]=0.f;
#pragma unroll
            for (int i=0;i<8;i++)  a9[i]=0.f;
        }
        if (c == 0){
#pragma unroll
            for (int i=0;i<16;i++) m0[i]=0.f;
        }
        if (c == 4){
#pragma unroll
            for (int i=0;i<16;i++) m1[i]=0.f;
        }

        uint32_t bb = sbase + OFF_B + (c&1)*16384;
#pragma unroll
        for (int p=0;p<2;p++){
            float acc0[16], acc1[16];
#pragma unroll
            for (int i=0;i<16;i++){ acc0[i]=0.f; acc1[i]=0.f; }
#pragma unroll
            for (int q4=0;q4<4;q4++){
#pragma unroll
                for (int nf=0;nf<4;nf++){
                    int nfg = p*4 + nf;
                    uint32_t bm[4];
                    ldsm4(bm, bb + (((nfg*8 + rowin)*16 + ((q4*4+mi) ^ rowin)) << 4));
                    mma16816(acc0 + nf*4, A0 + (2*q4)*4, bm[0], bm[1]);
                    mma16816(acc1 + nf*4, A1 + (2*q4)*4, bm[0], bm[1]);
                    if (q4 < 3){
                        mma16816(acc0 + nf*4, A0 + (2*q4+1)*4, bm[2], bm[3]);
                        mma16816(acc1 + nf*4, A1 + (2*q4+1)*4, bm[2], bm[3]);
                    }
                }
            }
            /* consume pass */
            if (c < 4){
#pragma unroll
                for (int nf=0;nf<4;nf++){
                    int u = c*4 + p*2 + (nf>>1);
                    int sl = (nf&1)*2;
                    float s0 = Fp0[u], s1 = Fp1[u], s2 = Fp2[u], s3 = Fp3[u];
                    m0[sl+0]  += acc0[nf*4+0]*s0;  m0[sl+1]  += acc0[nf*4+1]*s0;
                    m0[4+sl]  += acc0[nf*4+2]*s1;  m0[5+sl]  += acc0[nf*4+3]*s1;
                    m0[8+sl]  += acc1[nf*4+0]*s2;  m0[9+sl]  += acc1[nf*4+1]*s2;
                    m0[12+sl] += acc1[nf*4+2]*s3;  m0[13+sl] += acc1[nf*4+3]*s3;
                }
            } else if (c < 8){
#pragma unroll
                for (int nf=0;nf<4;nf++){
                    int u = (c-4)*4 + p*2 + (nf>>1);
                    int sl = (nf&1)*2;
                    float s0 = Fp0[u], s1 = Fp1[u], s2 = Fp2[u], s3 = Fp3[u];
                    m1[sl+0]  += acc0[nf*4+0]*s0;  m1[sl+1]  += acc0[nf*4+1]*s0;
                    m1[4+sl]  += acc0[nf*4+2]*s1;  m1[5+sl]  += acc0[nf*4+3]*s1;
                    m1[8+sl]  += acc1[nf*4+0]*s2;  m1[9+sl]  += acc1[nf*4+1]*s2;
                    m1[12+sl] += acc1[nf*4+2]*s3;  m1[13+sl] += acc1[nf*4+3]*s3;
                }
            } else if (c == 9){
#pragma unroll
                for (int nf=0;nf<4;nf++){
                    int u = p*4 + nf;
                    a9[0] += acc0[nf*4+0]*Fp0[40+u];  a9[1] += acc0[nf*4+1]*Fp0[40+u];
                    a9[2] += acc0[nf*4+2]*Fp1[40+u];  a9[3] += acc0[nf*4+3]*Fp1[40+u];
                    a9[4] += acc1[nf*4+0]*Fp2[40+u];  a9[5] += acc1[nf*4+1]*Fp2[40+u];
                    a9[6] += acc1[nf*4+2]*Fp3[40+u];  a9[7] += acc1[nf*4+3]*Fp3[40+u];
                }
            } else {  /* c==8 or c==10 */
                int fb = (c==8) ? 16 : 48;
#pragma unroll
                for (int nf=0;nf<4;nf++){
                    int u = p*4 + nf;
#pragma unroll
                    for (int d=0;d<3;d++){
                        a8[0+d]  += acc0[nf*4+0]*Fp0[fb+u*3+d];
                        a8[3+d]  += acc0[nf*4+1]*Fp0[fb+u*3+d];
                        a8[6+d]  += acc0[nf*4+2]*Fp1[fb+u*3+d];
                        a8[9+d]  += acc0[nf*4+3]*Fp1[fb+u*3+d];
                        a8[12+d] += acc1[nf*4+0]*Fp2[fb+u*3+d];
                        a8[15+d] += acc1[nf*4+1]*Fp2[fb+u*3+d];
                        a8[18+d] += acc1[nf*4+2]*Fp3[fb+u*3+d];
                        a8[21+d] += acc1[nf*4+3]*Fp3[fb+u*3+d];
                    }
                }
            }
        }

        /* flushes */
        if (c == 3){
            red2(&g_aggs[cn0*24 + tq],     m0[0]*C_SC,  m0[1]*C_SC);
            red2(&g_aggs[cn0*24 + 8 + tq], m0[2]*C_SC,  m0[3]*C_SC);
            red2(&g_aggs[cn1*24 + tq],     m0[4]*C_SC,  m0[5]*C_SC);
            red2(&g_aggs[cn1*24 + 8 + tq], m0[6]*C_SC,  m0[7]*C_SC);
            red2(&g_aggs[cn2*24 + tq],     m0[8]*C_SC,  m0[9]*C_SC);
            red2(&g_aggs[cn2*24 + 8 + tq], m0[10]*C_SC, m0[11]*C_SC);
            red2(&g_aggs[cn3*24 + tq],     m0[12]*C_SC, m0[13]*C_SC);
            red2(&g_aggs[cn3*24 + 8 + tq], m0[14]*C_SC, m0[15]*C_SC);
        } else if (c == 7){
            const float* Fs[4] = {Fp0, Fp1, Fp2, Fp3};
            int cns[4] = {cn0, cn1, cn2, cn3};
#pragma unroll
            for (int E=0;E<4;E++){
#pragma unroll
                for (int s=0;s<4;s++){
                    int t = (s>>1)*8 + tq + (s&1);
                    float f = m1[E*4+s]*C_SC;
                    red4(&g_aggv[cns[E]*128 + t*4], f*Fs[E][72], f*Fs[E][73], f*Fs[E][74]);
                }
            }
        } else if (c == 8){
            int cns[4] = {cn0, cn1, cn2, cn3};
#pragma unroll
            for (int E=0;E<4;E++){
                red4(&g_aggv[cns[E]*128 + (16+tq)*4],   a8[E*6+0]*C_V0, a8[E*6+1]*C_V0, a8[E*6+2]*C_V0);
                red4(&g_aggv[cns[E]*128 + (16+tq+1)*4], a8[E*6+3]*C_V0, a8[E*6+4]*C_V0, a8[E*6+5]*C_V0);
            }
        } else if (c == 9){
            red2(&g_aggs[cn0*24 + 16 + tq], a9[0]*C_CG, a9[1]*C_CG);
            red2(&g_aggs[cn1*24 + 16 + tq], a9[2]*C_CG, a9[3]*C_CG);
            red2(&g_aggs[cn2*24 + 16 + tq], a9[4]*C_CG, a9[5]*C_CG);
            red2(&g_aggs[cn3*24 + 16 + tq], a9[6]*C_CG, a9[7]*C_CG);
        } else if (c == 10){
            int cns[4] = {cn0, cn1, cn2, cn3};
#pragma unroll
            for (int E=0;E<4;E++){
                red4(&g_aggv[cns[E]*128 + (24+tq)*4],   a8[E*6+0]*C_CG, a8[E*6+1]*C_CG, a8[E*6+2]*C_CG);
                red4(&g_aggv[cns[E]*128 + (24+tq+1)*4], a8[E*6+3]*C_CG, a8[E*6+4]*C_CG, a8[E*6+5]*C_CG);
            }
        }

        cp_wait0();
        __syncthreads();
    }
}

/* ---------------- fused node update: blocks 0..624 = s, 625..937 = v ---------------- */
#define SBLK 625
__global__ void upd_kernel(int l, const float* __restrict__ lws, const float* __restrict__ lwv){
    int tid = threadIdx.x;
    if (blockIdx.x < SBLK){
        int idx = blockIdx.x*256 + tid;
        int n = idx>>4, t = idx&15;
        float a = 0.f;
#pragma unroll
        for (int u=0;u<24;u++) a += g_aggs[n*24+u]*lws[l*384+u*16+t];
        __syncthreads();
        g_s[idx] += a*I24;
        float4* z4 = (float4*)(g_aggs + (size_t)blockIdx.x*384);
        if (tid < 96) z4[tid] = make_float4(0.f,0.f,0.f,0.f);
    } else {
        int vb = blockIdx.x - SBLK;
        int idx = vb*256 + tid;
        bool act = idx < NN*8;
        int n = act ? (idx>>3) : 0, w = idx&7;
        float ax=0.f, ay=0.f, az=0.f;
        if (act){
            const float4* av = (const float4*)(g_aggv + (size_t)n*128);
#pragma unroll
            for (int u=0;u<32;u++){
                float lw = lwv[l*256+u*8+w];
                float4 a4 = av[u];
                ax += a4.x*lw; ay += a4.y*lw; az += a4.z*lw;
            }
        }
        __syncthreads();
        if (act){
            g_v[n*24+w*3+0] += ax*I32;
            g_v[n*24+w*3+1] += ay*I32;
            g_v[n*24+w*3+2] += az*I32;
        }
        size_t base4 = (size_t)vb*1024;
        float4* z4 = (float4*)g_aggv;
        float4 z = make_float4(0.f,0.f,0.f,0.f);
#pragma unroll
        for (int i=0;i<4;i++){
            size_t gi = base4 + tid + i*256;
            if (gi < (size_t)NN*32) z4[gi] = z;
        }
    }
}

/* ---------------- output ---------------- */
__global__ void out_kernel(const float* __restrict__ ow, float* __restrict__ out){
    int idx = blockIdx.x*256 + threadIdx.x;
    if (idx >= NN*8) return;
    int n = idx>>3, t = idx&7;
    float a = 0.f;
#pragma unroll
    for (int k=0;k<16;k++) a += g_s[n*16+k]*ow[k*8+t];
    out[idx] = a*I16;
}

/* ---------------- launch ---------------- */
extern "C" void kernel_launch(void* const* d_in, const int* in_sizes, int n_in,
                              void* d_out, int out_size){
    const float *x=0, *pos=0, *embed_w=0, *radial_w=0, *radial_b=0;
    const float *fc_w=0, *fc_b=0, *lin_ws=0, *lin_wv=0, *out_w=0;
    const int *ei=0;
    for (int i=0;i<n_in;i++){
        switch (in_sizes[i]){
            case 80000:  x=(const float*)d_in[i]; break;
            case 30000:  pos=(const float*)d_in[i]; break;
            case 4000:   radial_w=(const float*)d_in[i]; break;
            case 400:    radial_b=(const float*)d_in[i]; break;
            case 281600: fc_w=(const float*)d_in[i]; break;
            case 2816:   fc_b=(const float*)d_in[i]; break;
            case 1536:   lin_ws=(const float*)d_in[i]; break;
            case 1024:   lin_wv=(const float*)d_in[i]; break;
            case 320000: ei=(const int*)d_in[i]; break;
            case 128:
                if (!embed_w) embed_w=(const float*)d_in[i];
                else          out_w=(const float*)d_in[i];
                break;
        }
    }
    const int* row = ei;
    const int* col = ei + NE;
    float* out = (float*)d_out;

    cudaFuncSetAttribute(msg_kernel, cudaFuncAttributeMaxDynamicSharedMemorySize, SM_TOT);

    conv_fcw<<<(4*WN*KG + 255)/256, 256>>>(fc_w, fc_b);
    prol_kernel<<<1250, 256>>>(pos, row, col, x, embed_w, radial_w, radial_b);

    for (int l=0;l<4;l++){
        msg_kernel<<<NE/EB, 128, SM_TOT>>>(l, row, col);
        upd_kernel<<<SBLK + (NN*8 + 255)/256, 256>>>(l, lin_ws, lin_wv);
    }
    out_kernel<<<(NN*8+255)/256, 256>>>(out_w, out);
}

// round 17
// speedup vs baseline: 1.2250x; 1.0120x over previous
#include <cuda_runtime.h>
#include <cuda_fp16.h>
#include <math.h>
#include <stdint.h>

#define NN 10000
#define NE 160000
#define NB 10
#define RN 100
#define WN 704
#define NCH 11
#define EB 128
#define KG 128
#define HS 130        /* hh row stride in halves (conflict-free) */

#define SQ3    1.7320508075688772f
#define ISQ3   0.5773502691896258f
#define SQ75   2.7386127875258306f
#define C_SC   0.25f
#define C_V0   0.35355339059327373f
#define C_CG   0.20412414523193152f
#define I24    0.20412414523193152f
#define I32    0.17677669529663687f
#define I8     0.35355339059327373f
#define I16    0.25f
#define THIRD  0.3333333333333333f

__device__ float g_rbf[NE*12];       /* padded: 10 rbf + 2 unused, float4-aligned */
__device__ float g_sh1[NE*4];        /* padded: xyz + pad, float4-aligned */
__device__ float g_s[NN*16];
__device__ float g_v[NN*24];
__device__ float g_aggs[NN*24];
__device__ float g_aggv[NN*128];     /* [N][32][4] for float4 atomics */
__device__ uint16_t g_bt[4*WN*KG];   /* fc_w^T fp16, [l][n][k] padded */
__device__ float g_rwT[4*RN*12];     /* radial w transposed: [l][r][10 w + bias + pad] */

/* ---- smem layout (bytes) ----
   UNION @0: hh (128*130*2 = 33280) overlaid with feat (128*77*4 = 39424)
   COL   @39424 (512)
   B     @39936 (2 x 16384)                                              */
#define OFF_U    0
#define OFF_COL  39424
#define OFF_B    39936
#define SM_TOT   72704
#define FST 77

__device__ __forceinline__ uint32_t smem_u32(const void* p){
    uint32_t a; asm("{ .reg .u64 t; cvta.to.shared.u64 t, %1; cvt.u32.u64 %0, t; }":"=r"(a):"l"(p)); return a;
}
__device__ __forceinline__ void cpa16(uint32_t dst, const void* src){
    asm volatile("cp.async.ca.shared.global [%0], [%1], 16;"::"r"(dst),"l"(src):"memory");
}
__device__ __forceinline__ void cp_commit(){ asm volatile("cp.async.commit_group;":::"memory"); }
__device__ __forceinline__ void cp_wait0(){ asm volatile("cp.async.wait_group 0;":::"memory"); }
__device__ __forceinline__ void ldsm4(uint32_t* r, uint32_t a){
    asm volatile("ldmatrix.sync.aligned.m8n8.x4.shared.b16 {%0,%1,%2,%3}, [%4];"
        :"=r"(r[0]),"=r"(r[1]),"=r"(r[2]),"=r"(r[3]):"r"(a));
}
__device__ __forceinline__ void mma16816(float* d, const uint32_t* a, uint32_t b0, uint32_t b1){
    asm volatile("mma.sync.aligned.m16n8k16.row.col.f32.f16.f16.f32 "
        "{%0,%1,%2,%3}, {%4,%5,%6,%7}, {%8,%9}, {%0,%1,%2,%3};"
        : "+f"(d[0]),"+f"(d[1]),"+f"(d[2]),"+f"(d[3])
        : "r"(a[0]),"r"(a[1]),"r"(a[2]),"r"(a[3]),"r"(b0),"r"(b1));
}
__device__ __forceinline__ void red2(float* p, float a, float b){
    atomicAdd((float2*)p, make_float2(a,b));
}
__device__ __forceinline__ void red4(float* p, float a, float b, float c){
    atomicAdd((float4*)p, make_float4(a,b,c,0.f));
}

/* ---------------- fused prologue: geom | s-init | zeroing | rw transpose ---------------- */
__global__ void prol_kernel(const float* __restrict__ pos,
                            const int* __restrict__ row, const int* __restrict__ col,
                            const float* __restrict__ x, const float* __restrict__ ew,
                            const float* __restrict__ rw, const float* __restrict__ rb){
    int b = blockIdx.x, t = threadIdx.x;
    int gid = b*256 + t;

    if (b < 625){
        int e = gid;
        int r = row[e], c = col[e];
        float vx = pos[3*r]-pos[3*c], vy = pos[3*r+1]-pos[3*c+1], vz = pos[3*r+2]-pos[3*c+2];
        float len = sqrtf(vx*vx+vy*vy+vz*vz+1e-12f);
        float inv = 1.0f/len;
        *(float4*)(g_sh1 + (size_t)e*4) = make_float4(SQ3*vx*inv, SQ3*vy*inv, SQ3*vz*inv, 0.f);
        const float step = 10.0f/9.0f;
        float rb_[12];
#pragma unroll
        for (int k=0;k<NB;k++){ float d = len - (float)k*step; rb_[k] = expf(-0.405f*d*d); }
        rb_[10] = 0.f; rb_[11] = 0.f;
        float4* dst = (float4*)(g_rbf + (size_t)e*12);
        dst[0] = make_float4(rb_[0],rb_[1],rb_[2],rb_[3]);
        dst[1] = make_float4(rb_[4],rb_[5],rb_[6],rb_[7]);
        dst[2] = make_float4(rb_[8],rb_[9],rb_[10],rb_[11]);
    } else {
        int idx = (b-625)*256 + t;
        int n = idx>>4, tt = idx&15;
        float a = 0.f;
#pragma unroll
        for (int k=0;k<8;k++) a += x[n*8+k]*ew[k*16+tt];
        g_s[idx] = a*I8;
    }

    float4 z = make_float4(0.f,0.f,0.f,0.f);
    for (int i = gid; i < 440000; i += 320000){
        if (i < 60000)        ((float4*)g_aggs)[i] = z;
        else if (i < 120000)  ((float4*)g_v)[i-60000] = z;
        else                  ((float4*)g_aggv)[i-120000] = z;
    }
    if (gid < 4800){
        int j = gid % 12, r = (gid/12) % RN, l = gid / (RN*12);
        float v = 0.f;
        if (j < 10)       v = rw[l*1000 + j*100 + r];
        else if (j == 10) v = rb[l*100 + r];
        g_rwT[gid] = v;
    }
}

/* ---------------- one-time fc_w -> BT fp16 (padded K=128) ---------------- */
__global__ void conv_fcw(const float* __restrict__ fcw, const float* __restrict__ fcb){
    int idx = blockIdx.x*256 + threadIdx.x;
    if (idx >= 4*WN*KG) return;
    int k = idx & (KG-1);
    int n = (idx >> 7) % WN;
    int l = idx / (WN*KG);
    float v = 0.f;
    if (k < 100)       v = fcw[(size_t)(l*RN + k)*WN + n];
    else if (k == 100) v = fcb[l*WN + n];
    __half h = __float2half_rn(v);
    g_bt[idx] = *(uint16_t*)&h;
}

/* ---------------- fused HMMA message kernel: 4 warps, Tm=32 ---------------- */
__global__ void __launch_bounds__(128, 3)
msg_kernel(int l, const int* __restrict__ row, const int* __restrict__ col){
    extern __shared__ char smem[];
    uint32_t sbase = smem_u32(smem);
    int tid = threadIdx.x;
    int wid = tid>>5, lane = tid&31;
    int g = lane>>2, tig = lane&3;
    int mi = lane>>3, rowin = lane&7;
    int tq = tig*2;
    int e0 = blockIdx.x*EB;

    uint16_t* hh = (uint16_t*)(smem + OFF_U);
    float*    featf = (float*)(smem + OFF_U);
    int*      colsm = (int*)(smem + OFF_COL);

    /* stage B chunk 0 (1024 x 16B, 128 threads) */
    {
        const uint16_t* src = g_bt + (size_t)l*WN*KG;
#pragma unroll
        for (int i=0;i<8;i++){
            int cid = tid + i*128;
            int n = cid>>4, j = cid&15;
            cpa16(sbase + OFF_B + ((n*16 + (j ^ (n&7)))<<4), src + (size_t)n*KG + j*8);
        }
        cp_commit();
    }

    /* h compute: thread = edge, broadcast float4 LDG weights */
    {
        int eg = e0 + tid;
        float rbf[NB];
        {
            const float4* rb4 = (const float4*)(g_rbf + (size_t)eg*12);
            float4 a = rb4[0], b = rb4[1], c = rb4[2];
            rbf[0]=a.x; rbf[1]=a.y; rbf[2]=a.z; rbf[3]=a.w;
            rbf[4]=b.x; rbf[5]=b.y; rbf[6]=b.z; rbf[7]=b.w;
            rbf[8]=c.x; rbf[9]=c.y;
        }
        const float4* wt = (const float4*)(g_rwT + l*RN*12);
        uint16_t* hrow = hh + tid*HS;
#pragma unroll 4
        for (int r=0;r<RN;r++){
            float4 c0 = wt[r*3], c1 = wt[r*3+1], c2 = wt[r*3+2];
            float a = c2.z
                + rbf[0]*c0.x + rbf[1]*c0.y + rbf[2]*c0.z + rbf[3]*c0.w
                + rbf[4]*c1.x + rbf[5]*c1.y + rbf[6]*c1.z + rbf[7]*c1.w
                + rbf[8]*c2.x + rbf[9]*c2.y;
            a = fmaxf(a, 0.f);
            __half hv = __float2half_rn(a);
            hrow[r] = *(uint16_t*)&hv;
        }
        hrow[100] = 0x3C00;                 /* bias row: A = 1.0 */
#pragma unroll
        for (int r=101;r<112;r++) hrow[r] = 0;
    }
    __syncthreads();

    /* A fragment preload: warp strip = 32 edges (rows r0,+8 and r0+16,+24) */
    uint32_t A0[28], A1[28];
    int r0 = wid*32 + g;
    {
#pragma unroll
        for (int ks=0;ks<7;ks++){
            int k0 = ks*16 + tq;
            A0[ks*4+0] = *(uint32_t*)&hh[r0*HS + k0];
            A0[ks*4+1] = *(uint32_t*)&hh[(r0+8)*HS + k0];
            A0[ks*4+2] = *(uint32_t*)&hh[r0*HS + k0+8];
            A0[ks*4+3] = *(uint32_t*)&hh[(r0+8)*HS + k0+8];
            A1[ks*4+0] = *(uint32_t*)&hh[(r0+16)*HS + k0];
            A1[ks*4+1] = *(uint32_t*)&hh[(r0+24)*HS + k0];
            A1[ks*4+2] = *(uint32_t*)&hh[(r0+16)*HS + k0+8];
            A1[ks*4+3] = *(uint32_t*)&hh[(r0+24)*HS + k0+8];
        }
    }
    __syncthreads();   /* hh dead; feat overlays */

    /* features + col: thread = edge (vectorized gathers) */
    {
        int e = tid, eg = e0 + e;
        int rr = row[eg];
        colsm[e] = col[eg];
        float* F = featf + e*FST;
        {   /* g_s: 16 floats = 4 float4 */
            const float4* s4 = (const float4*)(g_s + (size_t)rr*16);
#pragma unroll
            for (int i=0;i<4;i++){
                float4 v = s4[i];
                F[i*4+0]=v.x; F[i*4+1]=v.y; F[i*4+2]=v.z; F[i*4+3]=v.w;
            }
        }
        {   /* g_v: 24 floats = 6 float4 */
            const float4* v4 = (const float4*)(g_v + (size_t)rr*24);
#pragma unroll
            for (int i=0;i<6;i++){
                float4 v = v4[i];
                F[16+i*4+0]=v.x; F[16+i*4+1]=v.y; F[16+i*4+2]=v.z; F[16+i*4+3]=v.w;
            }
        }
        float4 s1v = *(const float4*)(g_sh1 + (size_t)eg*4);
        float s1x = s1v.x, s1y = s1v.y, s1z = s1v.z;
        F[72]=s1x; F[73]=s1y; F[74]=s1z;
        float ux=s1x*ISQ3, uy=s1y*ISQ3, uz=s1z*ISQ3;
#pragma unroll
        for (int u=0;u<8;u++){
            float vx=F[16+u*3], vy=F[17+u*3], vz=F[18+u*3];
            float dot = ux*vx+uy*vy+uz*vz;
            F[40+u] = SQ3*dot;
            F[48+u*3] = SQ75*(dot*ux - vx*THIRD);
            F[49+u*3] = SQ75*(dot*uy - vy*THIRD);
            F[50+u*3] = SQ75*(dot*uz - vz*THIRD);
        }
    }
    cp_wait0();
    __syncthreads();

    const float* Fp0 = featf + r0*FST;
    const float* Fp1 = featf + (r0+8)*FST;
    const float* Fp2 = featf + (r0+16)*FST;
    const float* Fp3 = featf + (r0+24)*FST;
    int cn0 = colsm[r0], cn1 = colsm[r0+8], cn2 = colsm[r0+16], cn3 = colsm[r0+24];
    float m0[16], m1[16];

#pragma unroll
    for (int c=0;c<NCH;c++){
        if (c+1 < NCH){
            const uint16_t* src = g_bt + ((size_t)l*WN + (c+1)*64)*KG;
            uint32_t db = sbase + OFF_B + ((c+1)&1)*16384;
#pragma unroll
            for (int i=0;i<8;i++){
                int cid = tid + i*128;
                int n = cid>>4, j = cid&15;
                cpa16(db + ((n*16 + (j ^ (n&7)))<<4), src + (size_t)n*KG + j*8);
            }
            cp_commit();
        }

        float a8[24];
        float a9[8];
        if (c >= 8){
#pragma unroll
            for (int i=0;i<24;i++) a8[i]=0.f;
#pragma unroll
            for (int i=0;i<8;i++)  a9[i]=0.f;
        }
        if (c == 0){
#pragma unroll
            for (int i=0;i<16;i++) m0[i]=0.f;
        }
        if (c == 4){
#pragma unroll
            for (int i=0;i<16;i++) m1[i]=0.f;
        }

        uint32_t bb = sbase + OFF_B + (c&1)*16384;
#pragma unroll
        for (int p=0;p<2;p++){
            float acc0[16], acc1[16];
#pragma unroll
            for (int i=0;i<16;i++){ acc0[i]=0.f; acc1[i]=0.f; }
#pragma unroll
            for (int q4=0;q4<4;q4++){
#pragma unroll
                for (int nf=0;nf<4;nf++){
                    int nfg = p*4 + nf;
                    uint32_t bm[4];
                    ldsm4(bm, bb + (((nfg*8 + rowin)*16 + ((q4*4+mi) ^ rowin)) << 4));
                    mma16816(acc0 + nf*4, A0 + (2*q4)*4, bm[0], bm[1]);
                    mma16816(acc1 + nf*4, A1 + (2*q4)*4, bm[0], bm[1]);
                    if (q4 < 3){
                        mma16816(acc0 + nf*4, A0 + (2*q4+1)*4, bm[2], bm[3]);
                        mma16816(acc1 + nf*4, A1 + (2*q4+1)*4, bm[2], bm[3]);
                    }
                }
            }
            /* consume pass */
            if (c < 4){
#pragma unroll
                for (int nf=0;nf<4;nf++){
                    int u = c*4 + p*2 + (nf>>1);
                    int sl = (nf&1)*2;
                    float s0 = Fp0[u], s1 = Fp1[u], s2 = Fp2[u], s3 = Fp3[u];
                    m0[sl+0]  += acc0[nf*4+0]*s0;  m0[sl+1]  += acc0[nf*4+1]*s0;
                    m0[4+sl]  += acc0[nf*4+2]*s1;  m0[5+sl]  += acc0[nf*4+3]*s1;
                    m0[8+sl]  += acc1[nf*4+0]*s2;  m0[9+sl]  += acc1[nf*4+1]*s2;
                    m0[12+sl] += acc1[nf*4+2]*s3;  m0[13+sl] += acc1[nf*4+3]*s3;
                }
            } else if (c < 8){
#pragma unroll
                for (int nf=0;nf<4;nf++){
                    int u = (c-4)*4 + p*2 + (nf>>1);
                    int sl = (nf&1)*2;
                    float s0 = Fp0[u], s1 = Fp1[u], s2 = Fp2[u], s3 = Fp3[u];
                    m1[sl+0]  += acc0[nf*4+0]*s0;  m1[sl+1]  += acc0[nf*4+1]*s0;
                    m1[4+sl]  += acc0[nf*4+2]*s1;  m1[5+sl]  += acc0[nf*4+3]*s1;
                    m1[8+sl]  += acc1[nf*4+0]*s2;  m1[9+sl]  += acc1[nf*4+1]*s2;
                    m1[12+sl] += acc1[nf*4+2]*s3;  m1[13+sl] += acc1[nf*4+3]*s3;
                }
            } else if (c == 9){
#pragma unroll
                for (int nf=0;nf<4;nf++){
                    int u = p*4 + nf;
                    a9[0] += acc0[nf*4+0]*Fp0[40+u];  a9[1] += acc0[nf*4+1]*Fp0[40+u];
                    a9[2] += acc0[nf*4+2]*Fp1[40+u];  a9[3] += acc0[nf*4+3]*Fp1[40+u];
                    a9[4] += acc1[nf*4+0]*Fp2[40+u];  a9[5] += acc1[nf*4+1]*Fp2[40+u];
                    a9[6] += acc1[nf*4+2]*Fp3[40+u];  a9[7] += acc1[nf*4+3]*Fp3[40+u];
                }
            } else {  /* c==8 or c==10 */
                int fb = (c==8) ? 16 : 48;
#pragma unroll
                for (int nf=0;nf<4;nf++){
                    int u = p*4 + nf;
#pragma unroll
                    for (int d=0;d<3;d++){
                        a8[0+d]  += acc0[nf*4+0]*Fp0[fb+u*3+d];
                        a8[3+d]  += acc0[nf*4+1]*Fp0[fb+u*3+d];
                        a8[6+d]  += acc0[nf*4+2]*Fp1[fb+u*3+d];
                        a8[9+d]  += acc0[nf*4+3]*Fp1[fb+u*3+d];
                        a8[12+d] += acc1[nf*4+0]*Fp2[fb+u*3+d];
                        a8[15+d] += acc1[nf*4+1]*Fp2[fb+u*3+d];
                        a8[18+d] += acc1[nf*4+2]*Fp3[fb+u*3+d];
                        a8[21+d] += acc1[nf*4+3]*Fp3[fb+u*3+d];
                    }
                }
            }
        }

        /* flushes */
        if (c == 3){
            red2(&g_aggs[cn0*24 + tq],     m0[0]*C_SC,  m0[1]*C_SC);
            red2(&g_aggs[cn0*24 + 8 + tq], m0[2]*C_SC,  m0[3]*C_SC);
            red2(&g_aggs[cn1*24 + tq],     m0[4]*C_SC,  m0[5]*C_SC);
            red2(&g_aggs[cn1*24 + 8 + tq], m0[6]*C_SC,  m0[7]*C_SC);
            red2(&g_aggs[cn2*24 + tq],     m0[8]*C_SC,  m0[9]*C_SC);
            red2(&g_aggs[cn2*24 + 8 + tq], m0[10]*C_SC, m0[11]*C_SC);
            red2(&g_aggs[cn3*24 + tq],     m0[12]*C_SC, m0[13]*C_SC);
            red2(&g_aggs[cn3*24 + 8 + tq], m0[14]*C_SC, m0[15]*C_SC);
        } else if (c == 7){
            const float* Fs[4] = {Fp0, Fp1, Fp2, Fp3};
            int cns[4] = {cn0, cn1, cn2, cn3};
#pragma unroll
            for (int E=0;E<4;E++){
#pragma unroll
                for (int s=0;s<4;s++){
                    int t = (s>>1)*8 + tq + (s&1);
                    float f = m1[E*4+s]*C_SC;
                    red4(&g_aggv[cns[E]*128 + t*4], f*Fs[E][72], f*Fs[E][73], f*Fs[E][74]);
                }
            }
        } else if (c == 8){
            int cns[4] = {cn0, cn1, cn2, cn3};
#pragma unroll
            for (int E=0;E<4;E++){
                red4(&g_aggv[cns[E]*128 + (16+tq)*4],   a8[E*6+0]*C_V0, a8[E*6+1]*C_V0, a8[E*6+2]*C_V0);
                red4(&g_aggv[cns[E]*128 + (16+tq+1)*4], a8[E*6+3]*C_V0, a8[E*6+4]*C_V0, a8[E*6+5]*C_V0);
            }
        } else if (c == 9){
            red2(&g_aggs[cn0*24 + 16 + tq], a9[0]*C_CG, a9[1]*C_CG);
            red2(&g_aggs[cn1*24 + 16 + tq], a9[2]*C_CG, a9[3]*C_CG);
            red2(&g_aggs[cn2*24 + 16 + tq], a9[4]*C_CG, a9[5]*C_CG);
            red2(&g_aggs[cn3*24 + 16 + tq], a9[6]*C_CG, a9[7]*C_CG);
        } else if (c == 10){
            int cns[4] = {cn0, cn1, cn2, cn3};
#pragma unroll
            for (int E=0;E<4;E++){
                red4(&g_aggv[cns[E]*128 + (24+tq)*4],   a8[E*6+0]*C_CG, a8[E*6+1]*C_CG, a8[E*6+2]*C_CG);
                red4(&g_aggv[cns[E]*128 + (24+tq+1)*4], a8[E*6+3]*C_CG, a8[E*6+4]*C_CG, a8[E*6+5]*C_CG);
            }
        }

        cp_wait0();
        __syncthreads();
    }
}

/* ---------------- fused node update: blocks 0..624 = s, 625..937 = v ---------------- */
#define SBLK 625
__global__ void upd_kernel(int l, const float* __restrict__ lws, const float* __restrict__ lwv){
    int tid = threadIdx.x;
    if (blockIdx.x < SBLK){
        int idx = blockIdx.x*256 + tid;
        int n = idx>>4, t = idx&15;
        float a = 0.f;
#pragma unroll
        for (int u=0;u<24;u++) a += g_aggs[n*24+u]*lws[l*384+u*16+t];
        __syncthreads();
        g_s[idx] += a*I24;
        float4* z4 = (float4*)(g_aggs + (size_t)blockIdx.x*384);
        if (tid < 96) z4[tid] = make_float4(0.f,0.f,0.f,0.f);
    } else {
        int vb = blockIdx.x - SBLK;
        int idx = vb*256 + tid;
        bool act = idx < NN*8;
        int n = act ? (idx>>3) : 0, w = idx&7;
        float ax=0.f, ay=0.f, az=0.f;
        if (act){
            const float4* av = (const float4*)(g_aggv + (size_t)n*128);
#pragma unroll
            for (int u=0;u<32;u++){
                float lw = lwv[l*256+u*8+w];
                float4 a4 = av[u];
                ax += a4.x*lw; ay += a4.y*lw; az += a4.z*lw;
            }
        }
        __syncthreads();
        if (act){
            g_v[n*24+w*3+0] += ax*I32;
            g_v[n*24+w*3+1] += ay*I32;
            g_v[n*24+w*3+2] += az*I32;
        }
        size_t base4 = (size_t)vb*1024;
        float4* z4 = (float4*)g_aggv;
        float4 z = make_float4(0.f,0.f,0.f,0.f);
#pragma unroll
        for (int i=0;i<4;i++){
            size_t gi = base4 + tid + i*256;
            if (gi < (size_t)NN*32) z4[gi] = z;
        }
    }
}

/* ---------------- output (vectorized) ---------------- */
__global__ void out_kernel(const float* __restrict__ ow, float* __restrict__ out){
    int idx = blockIdx.x*256 + threadIdx.x;
    if (idx >= NN*8) return;
    int n = idx>>3, t = idx&7;
    const float4* s4 = (const float4*)(g_s + (size_t)n*16);
    float a = 0.f;
#pragma unroll
    for (int i=0;i<4;i++){
        float4 v = s4[i];
        a += v.x*ow[(i*4+0)*8+t] + v.y*ow[(i*4+1)*8+t]
           + v.z*ow[(i*4+2)*8+t] + v.w*ow[(i*4+3)*8+t];
    }
    out[idx] = a*I16;
}

/* ---------------- launch ---------------- */
extern "C" void kernel_launch(void* const* d_in, const int* in_sizes, int n_in,
                              void* d_out, int out_size){
    const float *x=0, *pos=0, *embed_w=0, *radial_w=0, *radial_b=0;
    const float *fc_w=0, *fc_b=0, *lin_ws=0, *lin_wv=0, *out_w=0;
    const int *ei=0;
    for (int i=0;i<n_in;i++){
        switch (in_sizes[i]){
            case 80000:  x=(const float*)d_in[i]; break;
            case 30000:  pos=(const float*)d_in[i]; break;
            case 4000:   radial_w=(const float*)d_in[i]; break;
            case 400:    radial_b=(const float*)d_in[i]; break;
            case 281600: fc_w=(const float*)d_in[i]; break;
            case 2816:   fc_b=(const float*)d_in[i]; break;
            case 1536:   lin_ws=(const float*)d_in[i]; break;
            case 1024:   lin_wv=(const float*)d_in[i]; break;
            case 320000: ei=(const int*)d_in[i]; break;
            case 128:
                if (!embed_w) embed_w=(const float*)d_in[i];
                else          out_w=(const float*)d_in[i];
                break;
        }
    }
    const int* row = ei;
    const int* col = ei + NE;
    float* out = (float*)d_out;

    cudaFuncSetAttribute(msg_kernel, cudaFuncAttributeMaxDynamicSharedMemorySize, SM_TOT);

    conv_fcw<<<(4*WN*KG + 255)/256, 256>>>(fc_w, fc_b);
    prol_kernel<<<1250, 256>>>(pos, row, col, x, embed_w, radial_w, radial_b);

    for (int l=0;l<4;l++){
        msg_kernel<<<NE/EB, 128, SM_TOT>>>(l, row, col);
        upd_kernel<<<SBLK + (NN*8 + 255)/256, 256>>>(l, lin_ws, lin_wv);
    }
    out_kernel<<<(NN*8+255)/256, 256>>>(out_w, out);
}